// round 3
// baseline (speedup 1.0000x reference)
#include <cuda_runtime.h>
#include <cuda_bf16.h>
#include <cstdint>
#include <math.h>

// ---------------- problem constants ----------------
#define S_LEN   8192
#define D_DIM   4096
#define NHEAD   8
#define NGROUP  4
#define HDIM    128
#define NQ      4096          // NHEAD*NGROUP*HDIM
#define NKC     1024          // NHEAD*HDIM
#define NB      (NQ + NKC)    // 5120 concat weight rows (q then k)
#define MT      128
#define NT      128
#define KCH     32            // K per pipeline chunk
#define NCH     (D_DIM / KCH) // 128
#define STAGES  4
#define NTILES_Q (NQ / NT)    // 32
#define NTILES  (NB / NT)     // 40
#define MTILES  (S_LEN / MT)  // 64

// ---------------- device-global scratch (no cudaMalloc allowed) ----------------
__device__ __align__(256) __nv_bfloat16 g_ah[(size_t)S_LEN * D_DIM];  // hs hi
__device__ __align__(256) __nv_bfloat16 g_al[(size_t)S_LEN * D_DIM];  // hs lo
__device__ __align__(256) __nv_bfloat16 g_bh[(size_t)NB * D_DIM];     // [q_w;k_w] hi
__device__ __align__(256) __nv_bfloat16 g_bl[(size_t)NB * D_DIM];     // [q_w;k_w] lo
__device__ float g_q[(size_t)S_LEN * NQ];   // [S, H, G, HD] normalized q
__device__ float g_k[(size_t)S_LEN * NKC];  // [S, H, HD]    normalized k

// ---------------- smem layout ----------------
#define SM_BIAS   0          // 128 floats
#define SM_NW     512        // 128 floats
#define SM_SS     1024       // 2 x 128 floats
#define SM_DATA   2048
#define STAGE_BYTES 32768    // Ahi 8K | Alo 8K | Bhi 8K | Blo 8K
#define SM_TOTAL  (SM_DATA + STAGES * STAGE_BYTES)   // 133120

// ---------------- PTX helpers ----------------
__device__ __forceinline__ uint32_t smem_to_u32(const void* p) {
    uint32_t a;
    asm("{ .reg .u64 t; cvta.to.shared.u64 t, %1; cvt.u32.u64 %0, t; }" : "=r"(a) : "l"(p));
    return a;
}
#define CP_ASYNC16(sa, ga) \
    asm volatile("cp.async.cg.shared.global [%0], [%1], 16;" :: "r"(sa), "l"(ga) : "memory")
#define CP_COMMIT() asm volatile("cp.async.commit_group;" ::: "memory")
#define CP_WAIT(n)  asm volatile("cp.async.wait_group %0;" :: "n"(n) : "memory")

#define LDMATRIX_X4(r0, r1, r2, r3, addr) \
    asm volatile("ldmatrix.sync.aligned.m8n8.x4.shared.b16 {%0,%1,%2,%3}, [%4];" \
        : "=r"(r0), "=r"(r1), "=r"(r2), "=r"(r3) : "r"(addr))

#define MMA_BF16(c, a, b0, b1) \
    asm volatile("mma.sync.aligned.m16n8k16.row.col.f32.bf16.bf16.f32 " \
        "{%0,%1,%2,%3}, {%4,%5,%6,%7}, {%8,%9}, {%0,%1,%2,%3};" \
        : "+f"((c)[0]), "+f"((c)[1]), "+f"((c)[2]), "+f"((c)[3]) \
        : "r"((a)[0]), "r"((a)[1]), "r"((a)[2]), "r"((a)[3]), "r"(b0), "r"(b1))

// ---------------- kernel 1: fp32 -> bf16 hi/lo split ----------------
#define HS4 ((S_LEN * (size_t)D_DIM) / 4)
#define QW4 ((NQ * (size_t)D_DIM) / 4)
#define KW4 ((NKC * (size_t)D_DIM) / 4)
#define TOT4 (HS4 + QW4 + KW4)

__global__ void __launch_bounds__(256)
convert_kernel(const float4* __restrict__ hs, const float4* __restrict__ qw,
               const float4* __restrict__ kw) {
    size_t stride = (size_t)gridDim.x * blockDim.x;
    for (size_t i = (size_t)blockIdx.x * blockDim.x + threadIdx.x; i < TOT4; i += stride) {
        const float4* src; uint2 *dh, *dl; size_t off;
        if (i < HS4)            { src = hs; off = i;             dh = (uint2*)g_ah; dl = (uint2*)g_al; }
        else if (i < HS4 + QW4) { src = qw; off = i - HS4;       dh = (uint2*)g_bh; dl = (uint2*)g_bl; }
        else                    { src = kw; off = i - HS4 - QW4; dh = (uint2*)g_bh + QW4; dl = (uint2*)g_bl + QW4; }
        float4 x = src[off];
        uint32_t h01, h23, l01, l23;
        asm("cvt.rn.bf16x2.f32 %0, %1, %2;" : "=r"(h01) : "f"(x.y), "f"(x.x));
        asm("cvt.rn.bf16x2.f32 %0, %1, %2;" : "=r"(h23) : "f"(x.w), "f"(x.z));
        float r0 = x.x - __uint_as_float(h01 << 16);
        float r1 = x.y - __uint_as_float(h01 & 0xffff0000u);
        float r2 = x.z - __uint_as_float(h23 << 16);
        float r3 = x.w - __uint_as_float(h23 & 0xffff0000u);
        asm("cvt.rn.bf16x2.f32 %0, %1, %2;" : "=r"(l01) : "f"(r1), "f"(r0));
        asm("cvt.rn.bf16x2.f32 %0, %1, %2;" : "=r"(l23) : "f"(r3), "f"(r2));
        dh[off] = make_uint2(h01, h23);
        dl[off] = make_uint2(l01, l23);
    }
}

// ---------------- kernel 2: pipelined bf16x3 mma.sync GEMM + bias + RMSNorm ----------------
__global__ void __launch_bounds__(256, 1)
gemm_norm_kernel(const float* __restrict__ q_b,
                 const float* __restrict__ q_nw, const float* __restrict__ k_nw) {
    extern __shared__ __align__(1024) char smem[];
    uint32_t sb = smem_to_u32(smem);
    int tid = threadIdx.x, wid = tid >> 5, lane = tid & 31;
    int wm = wid & 3, wn = wid >> 2;          // 4 x 2 warp grid; warp tile 32(M) x 64(N)

    int ntile = blockIdx.x, mtile = blockIdx.y;
    bool is_q = (ntile < NTILES_Q);
    const __nv_bfloat16* Ah = g_ah + (size_t)mtile * MT * D_DIM;
    const __nv_bfloat16* Al = g_al + (size_t)mtile * MT * D_DIM;
    const __nv_bfloat16* Bh = g_bh + (size_t)ntile * NT * D_DIM;
    const __nv_bfloat16* Bl = g_bl + (size_t)ntile * NT * D_DIM;
    const float* nw = is_q ? q_nw : k_nw;
    float* outp     = is_q ? g_q : g_k;
    int out_stride  = is_q ? NQ : NKC;
    int ncol0       = is_q ? ntile * NT : (ntile - NTILES_Q) * NT;

    if (tid < 128) {
        ((float*)(smem + SM_BIAS))[tid] = is_q ? q_b[ncol0 + tid] : 0.0f;
        ((float*)(smem + SM_NW))[tid]   = nw[tid];
    }
    __syncthreads();

    // ---- cp.async stage issue ----
    auto issue = [&](int c, int buf) {
        uint32_t base = sb + SM_DATA + (uint32_t)buf * STAGE_BYTES;
        int kc = c * KCH;
#pragma unroll
        for (int m = 0; m < 4; m++) {
            const __nv_bfloat16* src = (m == 0) ? Ah : (m == 1) ? Al : (m == 2) ? Bh : Bl;
            uint32_t mb = base + m * 8192;
#pragma unroll
            for (int it = 0; it < 2; it++) {
                int rc = tid + it * 256;     // 0..511
                int r = rc >> 2, cc = rc & 3;
                const void* gp = src + (size_t)r * D_DIM + kc + cc * 8;
                uint32_t sa = mb + r * 64 + ((cc ^ ((r >> 1) & 3)) * 16);
                CP_ASYNC16(sa, gp);
            }
        }
        CP_COMMIT();
    };

    issue(0, 0); issue(1, 1); issue(2, 2);

    float acc[2][8][4];
#pragma unroll
    for (int i = 0; i < 2; i++)
#pragma unroll
        for (int j = 0; j < 8; j++)
#pragma unroll
            for (int t = 0; t < 4; t++) acc[i][j][t] = 0.0f;

    // per-thread ldmatrix address components (fixed across chunks)
    int lrow = lane & 15;          // row within 16-row tile
    int csel = lane >> 4;          // k-halfchunk select (0: k0-7, 1: k8-15)
    // A rows for the two m16 tiles
    uint32_t a_row[2], a_sw[2];
#pragma unroll
    for (int i = 0; i < 2; i++) {
        int r = wm * 32 + i * 16 + lrow;
        a_row[i] = (uint32_t)r * 64;
        a_sw[i] = (r >> 1) & 3;
    }
    uint32_t b_row[4], b_sw[4];
#pragma unroll
    for (int j4 = 0; j4 < 4; j4++) {
        int r = wn * 64 + j4 * 16 + lrow;
        b_row[j4] = (uint32_t)r * 64;
        b_sw[j4] = (r >> 1) & 3;
    }

    for (int c = 0; c < NCH; c++) {
        int buf = c & 3;
        if (c + 3 < NCH) issue(c + 3, (c + 3) & 3); else CP_COMMIT();
        CP_WAIT(3);
        __syncthreads();
        uint32_t abase = sb + SM_DATA + (uint32_t)buf * STAGE_BYTES;
        uint32_t bbase = abase + 16384;
#pragma unroll
        for (int kh = 0; kh < 2; kh++) {
            uint32_t ah[2][4], al[2][4];
#pragma unroll
            for (int i = 0; i < 2; i++) {
                uint32_t pc = (uint32_t)((2 * kh + csel) ^ a_sw[i]) * 16;
                uint32_t ad = abase + a_row[i] + pc;
                LDMATRIX_X4(ah[i][0], ah[i][1], ah[i][2], ah[i][3], ad);
                LDMATRIX_X4(al[i][0], al[i][1], al[i][2], al[i][3], ad + 8192);
            }
            uint32_t bh[4][4], bl[4][4];
#pragma unroll
            for (int j4 = 0; j4 < 4; j4++) {
                uint32_t pc = (uint32_t)((2 * kh + csel) ^ b_sw[j4]) * 16;
                uint32_t bd = bbase + b_row[j4] + pc;
                LDMATRIX_X4(bh[j4][0], bh[j4][1], bh[j4][2], bh[j4][3], bd);
                LDMATRIX_X4(bl[j4][0], bl[j4][1], bl[j4][2], bl[j4][3], bd + 8192);
            }
#pragma unroll
            for (int i = 0; i < 2; i++) {
#pragma unroll
                for (int j = 0; j < 8; j++) {
                    int j4 = j >> 1, hb = j & 1;
                    uint32_t b0h = bh[j4][hb], b1h = bh[j4][2 + hb];
                    uint32_t b0l = bl[j4][hb], b1l = bl[j4][2 + hb];
                    MMA_BF16(acc[i][j], ah[i], b0h, b1h);   // hi*hi
                    MMA_BF16(acc[i][j], ah[i], b0l, b1l);   // hi*lo
                    MMA_BF16(acc[i][j], al[i], b0h, b1h);   // lo*hi
                }
            }
        }
        __syncthreads();   // release buffer (c) for reuse by issue at iteration c+1
    }

    // -------- epilogue: bias + RMSNorm over 128 cols (one head per CTA n-span) --------
    {
        const float* bias = (const float*)(smem + SM_BIAS);
        const float* nws  = (const float*)(smem + SM_NW);
        float* ssm = (float*)(smem + SM_SS);   // [2][128]

        float ssp[4] = {0.f, 0.f, 0.f, 0.f};   // (i, rh)
#pragma unroll
        for (int i = 0; i < 2; i++) {
#pragma unroll
            for (int j = 0; j < 8; j++) {
                int col = wn * 64 + j * 8 + (lane & 3) * 2;
                float b0 = bias[col], b1 = bias[col + 1];
                acc[i][j][0] += b0; acc[i][j][1] += b1;
                acc[i][j][2] += b0; acc[i][j][3] += b1;
                ssp[i * 2 + 0] += acc[i][j][0] * acc[i][j][0] + acc[i][j][1] * acc[i][j][1];
                ssp[i * 2 + 1] += acc[i][j][2] * acc[i][j][2] + acc[i][j][3] * acc[i][j][3];
            }
        }
#pragma unroll
        for (int r = 0; r < 4; r++) {
            ssp[r] += __shfl_xor_sync(0xffffffffu, ssp[r], 1);
            ssp[r] += __shfl_xor_sync(0xffffffffu, ssp[r], 2);
        }
        if ((lane & 3) == 0) {
#pragma unroll
            for (int r = 0; r < 4; r++) {
                int row = wm * 32 + (r >> 1) * 16 + (r & 1) * 8 + (lane >> 2);
                ssm[wn * 128 + row] = ssp[r];
            }
        }
        __syncthreads();
        float inv[4];
#pragma unroll
        for (int r = 0; r < 4; r++) {
            int row = wm * 32 + (r >> 1) * 16 + (r & 1) * 8 + (lane >> 2);
            float tot = ssm[row] + ssm[128 + row];
            inv[r] = rsqrtf(tot * (1.0f / 128.0f) + 1e-6f);
        }
        int row0 = mtile * MT;
#pragma unroll
        for (int i = 0; i < 2; i++) {
#pragma unroll
            for (int rh = 0; rh < 2; rh++) {
                int row = wm * 32 + i * 16 + rh * 8 + (lane >> 2);
                float iv = inv[i * 2 + rh];
                float* orow = outp + (size_t)(row0 + row) * out_stride + ncol0;
#pragma unroll
                for (int j = 0; j < 8; j++) {
                    int col = wn * 64 + j * 8 + (lane & 3) * 2;
                    float2 v;
                    v.x = acc[i][j][rh * 2 + 0] * iv * nws[col];
                    v.y = acc[i][j][rh * 2 + 1] * iv * nws[col + 1];
                    *(float2*)(orow + col) = v;
                }
            }
        }
    }
}

// ---------------- kernel 3: logistic gating score ----------------
__global__ void __launch_bounds__(128)
score_kernel(const float* __restrict__ kbase, const float* __restrict__ b,
             float* __restrict__ out) {
    int gw = (blockIdx.x * blockDim.x + threadIdx.x) >> 5;
    int lane = threadIdx.x & 31;
    int nwarps = (gridDim.x * blockDim.x) >> 5;
    const float inv_scale = 0.0883883476483184f;  // 1/sqrt(128)

    for (int task = gw; task < NHEAD * S_LEN; task += nwarps) {
        int h = task >> 13;          // out layout [1, H, S]
        int s = task & (S_LEN - 1);
        float4 kv = *(const float4*)(g_k + (size_t)s * NKC + h * HDIM + lane * 4);
        float4 kb = *(const float4*)(kbase + h * HDIM + lane * 4);
        float acc = 0.0f;
#pragma unroll
        for (int g = 0; g < NGROUP; g++) {
            float4 qv = *(const float4*)(g_q + (size_t)s * NQ + h * (NGROUP * HDIM) + g * HDIM + lane * 4);
            float dm = kv.x * qv.x + kv.y * qv.y + kv.z * qv.z + kv.w * qv.w;
            float db = kb.x * qv.x + kb.y * qv.y + kb.z * qv.z + kb.w * qv.w;
#pragma unroll
            for (int o = 16; o; o >>= 1) {
                dm += __shfl_xor_sync(0xffffffffu, dm, o);
                db += __shfl_xor_sync(0xffffffffu, db, o);
            }
            float logit = dm * inv_scale + b[h * NGROUP + g];
            float base  = db * inv_scale;
            acc += 1.0f / (1.0f + expf(base - logit));
        }
        if (lane == 0) out[task] = 0.25f * acc;
    }
}

// ---------------- launch ----------------
extern "C" void kernel_launch(void* const* d_in, const int* in_sizes, int n_in,
                              void* d_out, int out_size) {
    const float* hs    = (const float*)d_in[0];
    const float* q_w   = (const float*)d_in[1];
    const float* q_b   = (const float*)d_in[2];
    const float* k_w   = (const float*)d_in[3];
    const float* q_nw  = (const float*)d_in[4];
    const float* k_nw  = (const float*)d_in[5];
    const float* kbase = (const float*)d_in[6];
    const float* b     = (const float*)d_in[7];

    convert_kernel<<<8192, 256>>>((const float4*)hs, (const float4*)q_w, (const float4*)k_w);

    cudaFuncSetAttribute(gemm_norm_kernel,
                         cudaFuncAttributeMaxDynamicSharedMemorySize, SM_TOTAL);
    dim3 grid(NTILES, MTILES);  // ntile fastest: weight set swept per wave, stays L2-hot
    gemm_norm_kernel<<<grid, 256, SM_TOTAL>>>(q_b, q_nw, k_nw);

    score_kernel<<<2048, 128>>>(kbase, b, (float*)d_out);
}

// round 5
// speedup vs baseline: 1.1671x; 1.1671x over previous
#include <cuda_runtime.h>
#include <cuda_bf16.h>
#include <cstdint>
#include <math.h>

// ---------------- problem constants ----------------
#define S_LEN   8192
#define D_DIM   4096
#define NHEAD   8
#define NGROUP  4
#define HDIM    128
#define NQ      4096          // NHEAD*NGROUP*HDIM
#define NKC     1024          // NHEAD*HDIM
#define NB      (NQ + NKC)    // 5120 concat weight rows (q then k)
#define MT      128
#define NT      128
#define KCH     32            // K per pipeline chunk
#define NCH     (D_DIM / KCH) // 128
#define STAGES  3
#define NTILES_Q (NQ / NT)    // 32
#define NTILES  (NB / NT)     // 40
#define MTILES  (S_LEN / MT)  // 64

// ---------------- device-global scratch (no cudaMalloc allowed) ----------------
__device__ __align__(256) __nv_bfloat16 g_ah[(size_t)S_LEN * D_DIM];  // hs hi
__device__ __align__(256) __nv_bfloat16 g_al[(size_t)S_LEN * D_DIM];  // hs lo
__device__ __align__(256) __nv_bfloat16 g_bh[(size_t)NB * D_DIM];     // [q_w;k_w] hi
__device__ __align__(256) __nv_bfloat16 g_bl[(size_t)NB * D_DIM];     // [q_w;k_w] lo
__device__ float g_q[(size_t)S_LEN * NQ];   // [S, H, G, HD] normalized q
__device__ float g_k[(size_t)S_LEN * NKC];  // [S, H, HD]    normalized k

// ---------------- smem layout ----------------
#define SM_BIAS   0          // 128 floats
#define SM_NW     512        // 128 floats
#define SM_SS     1024       // 2 x 128 floats
#define SM_DATA   2048
#define STAGE_BYTES 32768    // Ahi 8K | Alo 8K | Bhi 8K | Blo 8K
#define SM_TOTAL  (SM_DATA + STAGES * STAGE_BYTES)   // 100352 -> 2 CTAs/SM

// ---------------- PTX helpers ----------------
__device__ __forceinline__ uint32_t smem_to_u32(const void* p) {
    uint32_t a;
    asm("{ .reg .u64 t; cvta.to.shared.u64 t, %1; cvt.u32.u64 %0, t; }" : "=r"(a) : "l"(p));
    return a;
}
#define CP_ASYNC16(sa, ga) \
    asm volatile("cp.async.cg.shared.global [%0], [%1], 16;" :: "r"(sa), "l"(ga) : "memory")
#define CP_COMMIT() asm volatile("cp.async.commit_group;" ::: "memory")
#define CP_WAIT(n)  asm volatile("cp.async.wait_group %0;" :: "n"(n) : "memory")

#define LDMATRIX_X4(r0, r1, r2, r3, addr) \
    asm volatile("ldmatrix.sync.aligned.m8n8.x4.shared.b16 {%0,%1,%2,%3}, [%4];" \
        : "=r"(r0), "=r"(r1), "=r"(r2), "=r"(r3) : "r"(addr))

#define MMA_BF16(c, a, b0, b1) \
    asm volatile("mma.sync.aligned.m16n8k16.row.col.f32.bf16.bf16.f32 " \
        "{%0,%1,%2,%3}, {%4,%5,%6,%7}, {%8,%9}, {%0,%1,%2,%3};" \
        : "+f"((c)[0]), "+f"((c)[1]), "+f"((c)[2]), "+f"((c)[3]) \
        : "r"((a)[0]), "r"((a)[1]), "r"((a)[2]), "r"((a)[3]), "r"(b0), "r"(b1))

// ---------------- kernel 1: fp32 -> bf16 hi/lo split ----------------
#define HS4 ((S_LEN * (size_t)D_DIM) / 4)
#define QW4 ((NQ * (size_t)D_DIM) / 4)
#define KW4 ((NKC * (size_t)D_DIM) / 4)
#define TOT4 (HS4 + QW4 + KW4)

__global__ void __launch_bounds__(256)
convert_kernel(const float4* __restrict__ hs, const float4* __restrict__ qw,
               const float4* __restrict__ kw) {
    size_t stride = (size_t)gridDim.x * blockDim.x;
    for (size_t i = (size_t)blockIdx.x * blockDim.x + threadIdx.x; i < TOT4; i += stride) {
        const float4* src; uint2 *dh, *dl; size_t off;
        if (i < HS4)            { src = hs; off = i;             dh = (uint2*)g_ah; dl = (uint2*)g_al; }
        else if (i < HS4 + QW4) { src = qw; off = i - HS4;       dh = (uint2*)g_bh; dl = (uint2*)g_bl; }
        else                    { src = kw; off = i - HS4 - QW4; dh = (uint2*)g_bh + QW4; dl = (uint2*)g_bl + QW4; }
        float4 x = src[off];
        uint32_t h01, h23, l01, l23;
        asm("cvt.rn.bf16x2.f32 %0, %1, %2;" : "=r"(h01) : "f"(x.y), "f"(x.x));
        asm("cvt.rn.bf16x2.f32 %0, %1, %2;" : "=r"(h23) : "f"(x.w), "f"(x.z));
        float r0 = x.x - __uint_as_float(h01 << 16);
        float r1 = x.y - __uint_as_float(h01 & 0xffff0000u);
        float r2 = x.z - __uint_as_float(h23 << 16);
        float r3 = x.w - __uint_as_float(h23 & 0xffff0000u);
        asm("cvt.rn.bf16x2.f32 %0, %1, %2;" : "=r"(l01) : "f"(r1), "f"(r0));
        asm("cvt.rn.bf16x2.f32 %0, %1, %2;" : "=r"(l23) : "f"(r3), "f"(r2));
        dh[off] = make_uint2(h01, h23);
        dl[off] = make_uint2(l01, l23);
    }
}

// ---------------- kernel 2: pipelined bf16x3 mma.sync GEMM + bias + RMSNorm ----------------
__global__ void __launch_bounds__(256, 2)
gemm_norm_kernel(const float* __restrict__ q_b,
                 const float* __restrict__ q_nw, const float* __restrict__ k_nw) {
    extern __shared__ __align__(1024) char smem[];
    uint32_t sb = smem_to_u32(smem);
    int tid = threadIdx.x, wid = tid >> 5, lane = tid & 31;
    int wm = wid & 3, wn = wid >> 2;          // 4 x 2 warp grid; warp tile 32(M) x 64(N)

    int ntile = blockIdx.x, mtile = blockIdx.y;
    bool is_q = (ntile < NTILES_Q);
    const __nv_bfloat16* Ah = g_ah + (size_t)mtile * MT * D_DIM;
    const __nv_bfloat16* Al = g_al + (size_t)mtile * MT * D_DIM;
    const __nv_bfloat16* Bh = g_bh + (size_t)ntile * NT * D_DIM;
    const __nv_bfloat16* Bl = g_bl + (size_t)ntile * NT * D_DIM;
    const float* nw = is_q ? q_nw : k_nw;
    float* outp     = is_q ? g_q : g_k;
    int out_stride  = is_q ? NQ : NKC;
    int ncol0       = is_q ? ntile * NT : (ntile - NTILES_Q) * NT;

    if (tid < 128) {
        ((float*)(smem + SM_BIAS))[tid] = is_q ? q_b[ncol0 + tid] : 0.0f;
        ((float*)(smem + SM_NW))[tid]   = nw[tid];
    }
    __syncthreads();

    // ---- cp.async stage issue ----
    auto issue = [&](int c, int buf) {
        uint32_t base = sb + SM_DATA + (uint32_t)buf * STAGE_BYTES;
        int kc = c * KCH;
#pragma unroll
        for (int m = 0; m < 4; m++) {
            const __nv_bfloat16* src = (m == 0) ? Ah : (m == 1) ? Al : (m == 2) ? Bh : Bl;
            uint32_t mb = base + m * 8192;
#pragma unroll
            for (int it = 0; it < 2; it++) {
                int rc = tid + it * 256;     // 0..511
                int r = rc >> 2, cc = rc & 3;
                const void* gp = src + (size_t)r * D_DIM + kc + cc * 8;
                uint32_t sa = mb + r * 64 + ((cc ^ ((r >> 1) & 3)) * 16);
                CP_ASYNC16(sa, gp);
            }
        }
        CP_COMMIT();
    };

    issue(0, 0); issue(1, 1);

    float acc[2][8][4];
#pragma unroll
    for (int i = 0; i < 2; i++)
#pragma unroll
        for (int j = 0; j < 8; j++)
#pragma unroll
            for (int t = 0; t < 4; t++) acc[i][j][t] = 0.0f;

    // per-thread ldmatrix address components (fixed across chunks)
    int lrow = lane & 15;          // row within 16-row tile
    int csel = lane >> 4;          // k-halfchunk select (0: k0-7, 1: k8-15)
    uint32_t a_row[2], a_sw[2];
#pragma unroll
    for (int i = 0; i < 2; i++) {
        int r = wm * 32 + i * 16 + lrow;
        a_row[i] = (uint32_t)r * 64;
        a_sw[i] = (r >> 1) & 3;
    }
    uint32_t b_row[4], b_sw[4];
#pragma unroll
    for (int j4 = 0; j4 < 4; j4++) {
        int r = wn * 64 + j4 * 16 + lrow;
        b_row[j4] = (uint32_t)r * 64;
        b_sw[j4] = (r >> 1) & 3;
    }

    for (int c = 0; c < NCH; c++) {
        int buf = c % 3;
        if (c + 2 < NCH) issue(c + 2, (c + 2) % 3); else CP_COMMIT();
        CP_WAIT(2);
        __syncthreads();
        uint32_t abase = sb + SM_DATA + (uint32_t)buf * STAGE_BYTES;
        uint32_t bbase = abase + 16384;
#pragma unroll
        for (int kh = 0; kh < 2; kh++) {
            uint32_t ah[2][4], al[2][4];
#pragma unroll
            for (int i = 0; i < 2; i++) {
                uint32_t pc = (uint32_t)((2 * kh + csel) ^ a_sw[i]) * 16;
                uint32_t ad = abase + a_row[i] + pc;
                LDMATRIX_X4(ah[i][0], ah[i][1], ah[i][2], ah[i][3], ad);
                LDMATRIX_X4(al[i][0], al[i][1], al[i][2], al[i][3], ad + 8192);
            }
#pragma unroll
            for (int j4 = 0; j4 < 4; j4++) {
                uint32_t bhf[4], blf[4];
                uint32_t pc = (uint32_t)((2 * kh + csel) ^ b_sw[j4]) * 16;
                uint32_t bd = bbase + b_row[j4] + pc;
                LDMATRIX_X4(bhf[0], bhf[1], bhf[2], bhf[3], bd);
                LDMATRIX_X4(blf[0], blf[1], blf[2], blf[3], bd + 8192);
#pragma unroll
                for (int i = 0; i < 2; i++) {
#pragma unroll
                    for (int hb = 0; hb < 2; hb++) {
                        int j = j4 * 2 + hb;
                        MMA_BF16(acc[i][j], ah[i], bhf[hb], bhf[2 + hb]);   // hi*hi
                        MMA_BF16(acc[i][j], ah[i], blf[hb], blf[2 + hb]);   // hi*lo
                        MMA_BF16(acc[i][j], al[i], bhf[hb], bhf[2 + hb]);   // lo*hi
                    }
                }
            }
        }
        __syncthreads();   // all warps done reading buf before it is re-filled next iter
    }

    // -------- epilogue: bias + RMSNorm over 128 cols (one head per CTA n-span) --------
    {
        const float* bias = (const float*)(smem + SM_BIAS);
        const float* nws  = (const float*)(smem + SM_NW);
        float* ssm = (float*)(smem + SM_SS);   // [2][128]

        float ssp[4] = {0.f, 0.f, 0.f, 0.f};   // (i, rh)
#pragma unroll
        for (int i = 0; i < 2; i++) {
#pragma unroll
            for (int j = 0; j < 8; j++) {
                int col = wn * 64 + j * 8 + (lane & 3) * 2;
                float b0 = bias[col], b1 = bias[col + 1];
                acc[i][j][0] += b0; acc[i][j][1] += b1;
                acc[i][j][2] += b0; acc[i][j][3] += b1;
                ssp[i * 2 + 0] += acc[i][j][0] * acc[i][j][0] + acc[i][j][1] * acc[i][j][1];
                ssp[i * 2 + 1] += acc[i][j][2] * acc[i][j][2] + acc[i][j][3] * acc[i][j][3];
            }
        }
#pragma unroll
        for (int r = 0; r < 4; r++) {
            ssp[r] += __shfl_xor_sync(0xffffffffu, ssp[r], 1);
            ssp[r] += __shfl_xor_sync(0xffffffffu, ssp[r], 2);
        }
        if ((lane & 3) == 0) {
#pragma unroll
            for (int r = 0; r < 4; r++) {
                int row = wm * 32 + (r >> 1) * 16 + (r & 1) * 8 + (lane >> 2);
                ssm[wn * 128 + row] = ssp[r];
            }
        }
        __syncthreads();
        float inv[4];
#pragma unroll
        for (int r = 0; r < 4; r++) {
            int row = wm * 32 + (r >> 1) * 16 + (r & 1) * 8 + (lane >> 2);
            float tot = ssm[row] + ssm[128 + row];
            inv[r] = rsqrtf(tot * (1.0f / 128.0f) + 1e-6f);
        }
        int row0 = mtile * MT;
#pragma unroll
        for (int i = 0; i < 2; i++) {
#pragma unroll
            for (int rh = 0; rh < 2; rh++) {
                int row = wm * 32 + i * 16 + rh * 8 + (lane >> 2);
                float iv = inv[i * 2 + rh];
                float* orow = outp + (size_t)(row0 + row) * out_stride + ncol0;
#pragma unroll
                for (int j = 0; j < 8; j++) {
                    int col = wn * 64 + j * 8 + (lane & 3) * 2;
                    float2 v;
                    v.x = acc[i][j][rh * 2 + 0] * iv * nws[col];
                    v.y = acc[i][j][rh * 2 + 1] * iv * nws[col + 1];
                    *(float2*)(orow + col) = v;
                }
            }
        }
    }
}

// ---------------- kernel 3: logistic gating score ----------------
__global__ void __launch_bounds__(128)
score_kernel(const float* __restrict__ kbase, const float* __restrict__ b,
             float* __restrict__ out) {
    int gw = (blockIdx.x * blockDim.x + threadIdx.x) >> 5;
    int lane = threadIdx.x & 31;
    int nwarps = (gridDim.x * blockDim.x) >> 5;
    const float inv_scale = 0.0883883476483184f;  // 1/sqrt(128)

    for (int task = gw; task < NHEAD * S_LEN; task += nwarps) {
        int h = task >> 13;          // out layout [1, H, S]
        int s = task & (S_LEN - 1);
        float4 kv = *(const float4*)(g_k + (size_t)s * NKC + h * HDIM + lane * 4);
        float4 kb = *(const float4*)(kbase + h * HDIM + lane * 4);
        float acc = 0.0f;
#pragma unroll
        for (int g = 0; g < NGROUP; g++) {
            float4 qv = *(const float4*)(g_q + (size_t)s * NQ + h * (NGROUP * HDIM) + g * HDIM + lane * 4);
            float dm = kv.x * qv.x + kv.y * qv.y + kv.z * qv.z + kv.w * qv.w;
            float db = kb.x * qv.x + kb.y * qv.y + kb.z * qv.z + kb.w * qv.w;
#pragma unroll
            for (int o = 16; o; o >>= 1) {
                dm += __shfl_xor_sync(0xffffffffu, dm, o);
                db += __shfl_xor_sync(0xffffffffu, db, o);
            }
            float logit = dm * inv_scale + b[h * NGROUP + g];
            float base  = db * inv_scale;
            acc += 1.0f / (1.0f + expf(base - logit));
        }
        if (lane == 0) out[task] = 0.25f * acc;
    }
}

// ---------------- launch ----------------
extern "C" void kernel_launch(void* const* d_in, const int* in_sizes, int n_in,
                              void* d_out, int out_size) {
    const float* hs    = (const float*)d_in[0];
    const float* q_w   = (const float*)d_in[1];
    const float* q_b   = (const float*)d_in[2];
    const float* k_w   = (const float*)d_in[3];
    const float* q_nw  = (const float*)d_in[4];
    const float* k_nw  = (const float*)d_in[5];
    const float* kbase = (const float*)d_in[6];
    const float* b     = (const float*)d_in[7];

    convert_kernel<<<8192, 256>>>((const float4*)hs, (const float4*)q_w, (const float4*)k_w);

    cudaFuncSetAttribute(gemm_norm_kernel,
                         cudaFuncAttributeMaxDynamicSharedMemorySize, SM_TOTAL);
    dim3 grid(NTILES, MTILES);  // ntile fastest: weight set swept per wave, stays L2-hot
    gemm_norm_kernel<<<grid, 256, SM_TOTAL>>>(q_b, q_nw, k_nw);

    score_kernel<<<2048, 128>>>(kbase, b, (float*)d_out);
}